// round 2
// baseline (speedup 1.0000x reference)
#include <cuda_runtime.h>
#include <cuda_fp16.h>
#include <cstdint>
#include <cstddef>

// ---------------- problem constants ----------------
#define N_HEADS 32
#define D_IN    1408
#define D_HID   256
#define D_OUT   3
#define BATCH   16384

// ---------------- GEMM tiling ----------------
#define M_TILE   128
#define N_TILE   256                 // one full head per CTA
#define K_TILE   64                  // fp16 elems -> 128 B per row
#define K_ITERS  (D_IN / K_TILE)     // 22
#define NSTAGES  4

#define A_STAGE_BYTES (M_TILE * K_TILE * 2)       // 16384
#define B_STAGE_BYTES (N_TILE * K_TILE * 2)       // 32768
#define STAGE_BYTES   (A_STAGE_BYTES + B_STAGE_BYTES)  // 49152
#define HDR_BYTES     5664
#define SMEM_SIZE     (6656 + NSTAGES * STAGE_BYTES)   // 203264 <= 227KB

// ---------------- device scratch ----------------
__device__ __half g_Xh[(size_t)BATCH * D_IN];                 // 46.1 MB
__device__ __half g_W1h[(size_t)N_HEADS * D_HID * D_IN];      // 23.1 MB (W1^T, K-major)

// ---------------- helpers ----------------
__device__ __forceinline__ uint32_t smem_u32(const void* p) {
    uint32_t a;
    asm("{ .reg .u64 t; cvta.to.shared.u64 t, %1; cvt.u32.u64 %0, t; }" : "=r"(a) : "l"(p));
    return a;
}

__device__ __forceinline__ void cp_async16(uint32_t saddr, const void* gaddr) {
    asm volatile("cp.async.cg.shared.global [%0], [%1], 16;" :: "r"(saddr), "l"(gaddr));
}

__device__ __forceinline__ void ldmatrix_x4(uint32_t* r, uint32_t addr) {
    asm volatile("ldmatrix.sync.aligned.m8n8.x4.shared.b16 {%0,%1,%2,%3}, [%4];"
                 : "=r"(r[0]), "=r"(r[1]), "=r"(r[2]), "=r"(r[3]) : "r"(addr));
}

__device__ __forceinline__ void mma16816(float* c, const uint32_t* a, uint32_t b0, uint32_t b1) {
    asm volatile(
        "mma.sync.aligned.m16n8k16.row.col.f32.f16.f16.f32 "
        "{%0,%1,%2,%3}, {%4,%5,%6,%7}, {%8,%9}, {%0,%1,%2,%3};"
        : "+f"(c[0]), "+f"(c[1]), "+f"(c[2]), "+f"(c[3])
        : "r"(a[0]), "r"(a[1]), "r"(a[2]), "r"(a[3]), "r"(b0), "r"(b1));
}

// ---------------- pre-pass 1: X fp32 -> fp16 rn ----------------
__global__ void k_convert_x(const float* __restrict__ X, int n4) {
    int i = blockIdx.x * blockDim.x + threadIdx.x;
    if (i >= n4) return;
    const float4 v = reinterpret_cast<const float4*>(X)[i];
    __half2* o2 = reinterpret_cast<__half2*>(g_Xh);
    o2[2 * i + 0] = __floats2half2_rn(v.x, v.y);
    o2[2 * i + 1] = __floats2half2_rn(v.z, v.w);
}

// ---------------- pre-pass 2: W1 [h][f][o] -> fp16 W1^T [h][o][f] ----------------
__global__ void k_transpose_w1(const float* __restrict__ W1) {
    __shared__ float tile[32][33];
    const int h  = blockIdx.z;
    const int f0 = blockIdx.x * 32;
    const int o0 = blockIdx.y * 32;
    const int tx = threadIdx.x, ty = threadIdx.y;   // 32 x 8
    const float* src = W1 + ((size_t)h * D_IN + f0) * D_HID + o0;
    #pragma unroll
    for (int r = 0; r < 32; r += 8)
        tile[ty + r][tx] = src[(size_t)(ty + r) * D_HID + tx];
    __syncthreads();
    __half* dst = g_W1h + ((size_t)h * D_HID + o0) * D_IN + f0;
    #pragma unroll
    for (int r = 0; r < 32; r += 8)
        dst[(size_t)(ty + r) * D_IN + tx] = __float2half_rn(tile[tx][ty + r]);
}

// ---------------- main fused GEMM ----------------
// grid = (BATCH/M_TILE, N_HEADS), 256 threads (8 warps: 2 along M x 4 along N).
// Warp tile 64x64 via mma.sync m16n8k16.  4-stage cp.async pipeline.
__global__ void __launch_bounds__(256, 1)
k_gemm(const float* __restrict__ b1,
       const float* __restrict__ W2,
       const float* __restrict__ b2,
       float* __restrict__ out)
{
    extern __shared__ char smem[];
    float* s_red = (float*)(smem);           // 128*3 floats
    float* s_b1  = (float*)(smem + 1536);    // 256 floats
    float* s_W2  = (float*)(smem + 2560);    // 768 floats
    float* s_b2  = (float*)(smem + 5632);    // 3 floats

    const int tid = threadIdx.x;
    const int w   = tid >> 5;
    const int l   = tid & 31;
    const int mw  = w >> 2;          // 0..1
    const int nw  = w & 3;           // 0..3
    const int mtile = blockIdx.x;
    const int head  = blockIdx.y;

    const uint32_t sbase  = smem_u32(smem);
    const uint32_t tiles0 = (sbase + HDR_BYTES + 1023u) & ~1023u;   // 1024-aligned tile area

    // header init
    for (int i = tid; i < M_TILE * 3; i += 256) s_red[i] = 0.0f;
    for (int i = tid; i < D_HID; i += 256)      s_b1[i] = b1[head * D_HID + i];
    for (int i = tid; i < D_HID * 3; i += 256)  s_W2[i] = W2[head * D_HID * 3 + i];
    if (tid < 3)                                s_b2[tid] = b2[head * 3 + tid];
    __syncthreads();

    const __half* gA = g_Xh  + (size_t)(mtile * M_TILE) * D_IN;
    const __half* gB = g_W1h + (size_t)(head * D_HID) * D_IN;

    // -------- cp.async stage issue (each thread: 4 A chunks + 8 B chunks of 16B) --------
    const int r8 = tid >> 3;              // 0..31
    const int cc = tid & 7;               // 16B chunk within 128B row
    const uint32_t physc = (uint32_t)(cc ^ (r8 & 7)) * 16;   // XOR swizzle

    auto issue_stage = [&](int slot, int kiter) {
        const uint32_t st = tiles0 + slot * STAGE_BYTES;
        const int k0 = kiter * K_TILE;
        #pragma unroll
        for (int j = 0; j < 4; j++) {                 // A: 128 rows
            const int row = j * 32 + r8;
            cp_async16(st + row * 128 + physc, gA + (size_t)row * D_IN + k0 + cc * 8);
        }
        #pragma unroll
        for (int j = 0; j < 8; j++) {                 // B: 256 rows
            const int row = j * 32 + r8;
            cp_async16(st + A_STAGE_BYTES + row * 128 + physc,
                       gB + (size_t)row * D_IN + k0 + cc * 8);
        }
        asm volatile("cp.async.commit_group;" ::: "memory");
    };

    // -------- accumulators --------
    float acc[4][8][4];
    #pragma unroll
    for (int mi = 0; mi < 4; mi++)
        #pragma unroll
        for (int ni = 0; ni < 8; ni++)
            #pragma unroll
            for (int t = 0; t < 4; t++) acc[mi][ni][t] = 0.0f;

    // ldmatrix lane addressing (within-stage, swizzled)
    const int a_row_in16 = l & 15;        // A: row offset within m16
    const int a_cadd     = l >> 4;        // A: +1 chunk for k8..15
    const int b_row_in16 = ((l >> 4) << 3) + (l & 7);   // B: row offset within n16
    const int b_cadd     = (l >> 3) & 1;

    // prologue
    issue_stage(0, 0);
    issue_stage(1, 1);
    issue_stage(2, 2);

    for (int i = 0; i < K_ITERS; i++) {
        asm volatile("cp.async.wait_group 2;" ::: "memory");
        __syncthreads();

        if (i + 3 < K_ITERS) issue_stage((i + 3) & 3, i + 3);
        else                 asm volatile("cp.async.commit_group;" ::: "memory");

        const uint32_t stA = tiles0 + (i & 3) * STAGE_BYTES;
        const uint32_t stB = stA + A_STAGE_BYTES;

        #pragma unroll
        for (int ks = 0; ks < 4; ks++) {             // 4 x k16
            const int c0 = ks * 2;                    // 16B-chunk index of k-step
            uint32_t af[4][4];
            #pragma unroll
            for (int mi = 0; mi < 4; mi++) {
                const int row = mw * 64 + mi * 16 + a_row_in16;
                const int ch  = c0 + a_cadd;
                ldmatrix_x4(af[mi], stA + row * 128 + ((uint32_t)(ch ^ (row & 7)) * 16));
            }
            uint32_t bf[4][4];
            #pragma unroll
            for (int nj = 0; nj < 4; nj++) {         // 4 x n16
                const int row = nw * 64 + nj * 16 + b_row_in16;
                const int ch  = c0 + b_cadd;
                ldmatrix_x4(bf[nj], stB + row * 128 + ((uint32_t)(ch ^ (row & 7)) * 16));
            }
            #pragma unroll
            for (int mi = 0; mi < 4; mi++)
                #pragma unroll
                for (int nj = 0; nj < 4; nj++) {
                    mma16816(acc[mi][2 * nj],     af[mi], bf[nj][0], bf[nj][1]);
                    mma16816(acc[mi][2 * nj + 1], af[mi], bf[nj][2], bf[nj][3]);
                }
        }
    }

    // -------- epilogue: h = relu(acc + b1), partial out = h @ W2 --------
    float part[8][3];
    #pragma unroll
    for (int r = 0; r < 8; r++) { part[r][0] = part[r][1] = part[r][2] = 0.0f; }

    #pragma unroll
    for (int mi = 0; mi < 4; mi++)
        #pragma unroll
        for (int ni = 0; ni < 8; ni++)
            #pragma unroll
            for (int t2 = 0; t2 < 4; t2++) {
                const int q = t2 >> 1, t = t2 & 1;
                const int n = nw * 64 + ni * 8 + (l & 3) * 2 + t;
                float h = acc[mi][ni][t2] + s_b1[n];
                h = fmaxf(h, 0.0f);
                part[mi * 2 + q][0] = fmaf(h, s_W2[n * 3 + 0], part[mi * 2 + q][0]);
                part[mi * 2 + q][1] = fmaf(h, s_W2[n * 3 + 1], part[mi * 2 + q][1]);
                part[mi * 2 + q][2] = fmaf(h, s_W2[n * 3 + 2], part[mi * 2 + q][2]);
            }

    // reduce over the 4 lanes sharing each row (l&3 varies)
    #pragma unroll
    for (int r = 0; r < 8; r++)
        #pragma unroll
        for (int p = 0; p < 3; p++) {
            part[r][p] += __shfl_xor_sync(0xffffffffu, part[r][p], 1);
            part[r][p] += __shfl_xor_sync(0xffffffffu, part[r][p], 2);
        }

    if ((l & 3) == 0) {
        #pragma unroll
        for (int mi = 0; mi < 4; mi++)
            #pragma unroll
            for (int q = 0; q < 2; q++) {
                const int row = mw * 64 + mi * 16 + (l >> 2) + q * 8;
                atomicAdd(&s_red[row * 3 + 0], part[mi * 2 + q][0]);
                atomicAdd(&s_red[row * 3 + 1], part[mi * 2 + q][1]);
                atomicAdd(&s_red[row * 3 + 2], part[mi * 2 + q][2]);
            }
    }
    __syncthreads();

    if (tid < M_TILE) {
        float* po = out + (size_t)(mtile * M_TILE + tid) * (N_HEADS * D_OUT) + head * 3;
        po[0] = s_red[tid * 3 + 0] + s_b2[0];
        po[1] = s_red[tid * 3 + 1] + s_b2[1];
        po[2] = s_red[tid * 3 + 2] + s_b2[2];
    }
}

// ---------------- host launch ----------------
extern "C" void kernel_launch(void* const* d_in, const int* in_sizes, int n_in,
                              void* d_out, int out_size) {
    const float* X  = (const float*)d_in[0];
    const float* W1 = (const float*)d_in[1];
    const float* b1 = (const float*)d_in[2];
    const float* W2 = (const float*)d_in[3];
    const float* b2 = (const float*)d_in[4];
    float* out = (float*)d_out;
    (void)in_sizes; (void)n_in; (void)out_size;

    {
        const int n4 = (BATCH * D_IN) / 4;
        k_convert_x<<<(n4 + 255) / 256, 256>>>(X, n4);
        dim3 tg(D_IN / 32, D_HID / 32, N_HEADS);   // (44, 8, 32)
        k_transpose_w1<<<tg, dim3(32, 8)>>>(W1);
    }

    static bool attr_set = false;
    if (!attr_set) {
        cudaFuncSetAttribute(k_gemm, cudaFuncAttributeMaxDynamicSharedMemorySize, SMEM_SIZE);
        attr_set = true;
    }
    dim3 grid(BATCH / M_TILE, N_HEADS);
    k_gemm<<<grid, 256, SMEM_SIZE>>>(b1, W2, b2, out);
}

// round 3
// speedup vs baseline: 1.0048x; 1.0048x over previous
#include <cuda_runtime.h>
#include <cuda_fp16.h>
#include <cstdint>
#include <cstddef>

// ---------------- problem constants ----------------
#define N_HEADS 32
#define D_IN    1408
#define D_HID   256
#define D_OUT   3
#define BATCH   16384

// ---------------- GEMM tiling ----------------
#define M_TILE   128
#define N_TILE   256                 // one full head per CTA
#define K_TILE   64                  // fp16 elems -> 128 B per row
#define K_ITERS  (D_IN / K_TILE)     // 22
#define NSTAGES  4

#define A_STAGE_BYTES (M_TILE * K_TILE * 2)       // 16384
#define B_STAGE_BYTES (N_TILE * K_TILE * 2)       // 32768
#define STAGE_BYTES   (A_STAGE_BYTES + B_STAGE_BYTES)  // 49152
#define HDR_BYTES     5664
#define SMEM_SIZE     (6656 + NSTAGES * STAGE_BYTES)   // 203264 <= 227KB

// prepass grid split
#define CONV_BLOCKS  ((BATCH * D_IN) / 4 / 256)        // 22528
#define TRANS_BLOCKS (N_HEADS * (D_IN / 32) * (D_HID / 32))  // 11264

// ---------------- device scratch ----------------
__device__ __half g_Xh[(size_t)BATCH * D_IN];                 // 46.1 MB
__device__ __half g_W1h[(size_t)N_HEADS * D_HID * D_IN];      // 23.1 MB (W1^T, K-major)

// ---------------- helpers ----------------
__device__ __forceinline__ uint32_t smem_u32(const void* p) {
    uint32_t a;
    asm("{ .reg .u64 t; cvta.to.shared.u64 t, %1; cvt.u32.u64 %0, t; }" : "=r"(a) : "l"(p));
    return a;
}

__device__ __forceinline__ void cp_async16(uint32_t saddr, const void* gaddr) {
    asm volatile("cp.async.cg.shared.global [%0], [%1], 16;" :: "r"(saddr), "l"(gaddr));
}

__device__ __forceinline__ void ldmatrix_x4(uint32_t* r, uint32_t addr) {
    asm volatile("ldmatrix.sync.aligned.m8n8.x4.shared.b16 {%0,%1,%2,%3}, [%4];"
                 : "=r"(r[0]), "=r"(r[1]), "=r"(r[2]), "=r"(r[3]) : "r"(addr));
}

__device__ __forceinline__ void mma16816(float* c, const uint32_t* a, uint32_t b0, uint32_t b1) {
    asm volatile(
        "mma.sync.aligned.m16n8k16.row.col.f32.f16.f16.f32 "
        "{%0,%1,%2,%3}, {%4,%5,%6,%7}, {%8,%9}, {%0,%1,%2,%3};"
        : "+f"(c[0]), "+f"(c[1]), "+f"(c[2]), "+f"(c[3])
        : "r"(a[0]), "r"(a[1]), "r"(a[2]), "r"(a[3]), "r"(b0), "r"(b1));
}

// ---------------- merged pre-pass: convert X + transpose W1 ----------------
// blocks [0, CONV_BLOCKS)                : X fp32 -> fp16 rn   (256 thr, 4 float4 each)
// blocks [CONV_BLOCKS, CONV+TRANS)       : W1 [h][f][o] -> fp16 W1^T [h][o][f]
__global__ void __launch_bounds__(256)
k_prepass(const float* __restrict__ X, const float* __restrict__ W1) {
    const int tid = threadIdx.x;
    if (blockIdx.x < CONV_BLOCKS) {
        const int i = blockIdx.x * 256 + tid;
        const float4 v = reinterpret_cast<const float4*>(X)[i];
        __half2* o2 = reinterpret_cast<__half2*>(g_Xh);
        o2[2 * i + 0] = __floats2half2_rn(v.x, v.y);
        o2[2 * i + 1] = __floats2half2_rn(v.z, v.w);
    } else {
        __shared__ float tile[32][33];
        const int b   = blockIdx.x - CONV_BLOCKS;
        const int h   = b / ((D_IN / 32) * (D_HID / 32));
        const int rem = b % ((D_IN / 32) * (D_HID / 32));
        const int f0  = (rem % (D_IN / 32)) * 32;
        const int o0  = (rem / (D_IN / 32)) * 32;
        const int tx = tid & 31, ty = tid >> 5;     // 32 x 8
        const float* src = W1 + ((size_t)h * D_IN + f0) * D_HID + o0;
        #pragma unroll
        for (int r = 0; r < 32; r += 8)
            tile[ty + r][tx] = src[(size_t)(ty + r) * D_HID + tx];
        __syncthreads();
        __half* dst = g_W1h + ((size_t)h * D_HID + o0) * D_IN + f0;
        #pragma unroll
        for (int r = 0; r < 32; r += 8)
            dst[(size_t)(ty + r) * D_IN + tx] = __float2half_rn(tile[tx][ty + r]);
    }
}

// ---------------- main fused GEMM ----------------
// grid = (BATCH/M_TILE, N_HEADS), 256 threads (8 warps: 2 along M x 4 along N).
// Warp tile 64x64 via mma.sync m16n8k16. 4-stage cp.async pipeline.
// Register double-buffered ldmatrix fragments (prefetch ks+1 during ks MMAs).
__global__ void __launch_bounds__(256, 1)
k_gemm(const float* __restrict__ b1,
       const float* __restrict__ W2,
       const float* __restrict__ b2,
       float* __restrict__ out)
{
    extern __shared__ char smem[];
    float* s_red = (float*)(smem);           // 128*3 floats
    float* s_b1  = (float*)(smem + 1536);    // 256 floats
    float* s_W2  = (float*)(smem + 2560);    // 768 floats
    float* s_b2  = (float*)(smem + 5632);    // 3 floats

    const int tid = threadIdx.x;
    const int w   = tid >> 5;
    const int l   = tid & 31;
    const int mw  = w >> 2;          // 0..1
    const int nw  = w & 3;           // 0..3
    const int mtile = blockIdx.x;
    const int head  = blockIdx.y;

    const uint32_t sbase  = smem_u32(smem);
    const uint32_t tiles0 = (sbase + HDR_BYTES + 1023u) & ~1023u;   // 1024-aligned tile area

    // header init
    for (int i = tid; i < M_TILE * 3; i += 256) s_red[i] = 0.0f;
    for (int i = tid; i < D_HID; i += 256)      s_b1[i] = b1[head * D_HID + i];
    for (int i = tid; i < D_HID * 3; i += 256)  s_W2[i] = W2[head * D_HID * 3 + i];
    if (tid < 3)                                s_b2[tid] = b2[head * 3 + tid];
    __syncthreads();

    const __half* gA = g_Xh  + (size_t)(mtile * M_TILE) * D_IN;
    const __half* gB = g_W1h + (size_t)(head * D_HID) * D_IN;

    // -------- cp.async stage issue (each thread: 4 A chunks + 8 B chunks of 16B) --------
    const int r8 = tid >> 3;              // 0..31
    const int cc = tid & 7;               // 16B chunk within 128B row
    const uint32_t physc = (uint32_t)(cc ^ (r8 & 7)) * 16;   // XOR swizzle

    auto issue_stage = [&](int slot, int kiter) {
        const uint32_t st = tiles0 + slot * STAGE_BYTES;
        const int k0 = kiter * K_TILE;
        #pragma unroll
        for (int j = 0; j < 4; j++) {                 // A: 128 rows
            const int row = j * 32 + r8;
            cp_async16(st + row * 128 + physc, gA + (size_t)row * D_IN + k0 + cc * 8);
        }
        #pragma unroll
        for (int j = 0; j < 8; j++) {                 // B: 256 rows
            const int row = j * 32 + r8;
            cp_async16(st + A_STAGE_BYTES + row * 128 + physc,
                       gB + (size_t)row * D_IN + k0 + cc * 8);
        }
        asm volatile("cp.async.commit_group;" ::: "memory");
    };

    // -------- accumulators --------
    float acc[4][8][4];
    #pragma unroll
    for (int mi = 0; mi < 4; mi++)
        #pragma unroll
        for (int ni = 0; ni < 8; ni++)
            #pragma unroll
            for (int t = 0; t < 4; t++) acc[mi][ni][t] = 0.0f;

    // ldmatrix lane addressing (within-stage, swizzled)
    const int a_row_in16 = l & 15;        // A: row offset within m16
    const int a_cadd     = l >> 4;        // A: +1 chunk for k8..15
    const int b_row_in16 = ((l >> 4) << 3) + (l & 7);   // B: row offset within n16
    const int b_cadd     = (l >> 3) & 1;

    // fragment double buffers
    uint32_t af[2][4][4];
    uint32_t bf[2][4][4];

    auto load_frags = [&](int buf, uint32_t stA, uint32_t stB, int ks) {
        const int c0 = ks * 2;
        #pragma unroll
        for (int mi = 0; mi < 4; mi++) {
            const int row = mw * 64 + mi * 16 + a_row_in16;
            const int ch  = c0 + a_cadd;
            ldmatrix_x4(af[buf][mi], stA + row * 128 + ((uint32_t)(ch ^ (row & 7)) * 16));
        }
        #pragma unroll
        for (int nj = 0; nj < 4; nj++) {
            const int row = nw * 64 + nj * 16 + b_row_in16;
            const int ch  = c0 + b_cadd;
            ldmatrix_x4(bf[buf][nj], stB + row * 128 + ((uint32_t)(ch ^ (row & 7)) * 16));
        }
    };

    auto do_mmas = [&](int buf) {
        #pragma unroll
        for (int mi = 0; mi < 4; mi++)
            #pragma unroll
            for (int nj = 0; nj < 4; nj++) {
                mma16816(acc[mi][2 * nj],     af[buf][mi], bf[buf][nj][0], bf[buf][nj][1]);
                mma16816(acc[mi][2 * nj + 1], af[buf][mi], bf[buf][nj][2], bf[buf][nj][3]);
            }
    };

    // prologue
    issue_stage(0, 0);
    issue_stage(1, 1);
    issue_stage(2, 2);

    for (int i = 0; i < K_ITERS; i++) {
        asm volatile("cp.async.wait_group 2;" ::: "memory");
        __syncthreads();

        const uint32_t stA = tiles0 + (i & 3) * STAGE_BYTES;
        const uint32_t stB = stA + A_STAGE_BYTES;

        // first fragments on the critical path, then kick off next stage's loads
        load_frags(0, stA, stB, 0);

        if (i + 3 < K_ITERS) issue_stage((i + 3) & 3, i + 3);
        else                 asm volatile("cp.async.commit_group;" ::: "memory");

        // software-pipelined: prefetch ks+1 while doing ks's MMAs
        load_frags(1, stA, stB, 1);
        do_mmas(0);
        load_frags(0, stA, stB, 2);
        do_mmas(1);
        load_frags(1, stA, stB, 3);
        do_mmas(0);
        do_mmas(1);
    }

    // -------- epilogue: h = relu(acc + b1), partial out = h @ W2 --------
    float part[8][3];
    #pragma unroll
    for (int r = 0; r < 8; r++) { part[r][0] = part[r][1] = part[r][2] = 0.0f; }

    #pragma unroll
    for (int mi = 0; mi < 4; mi++)
        #pragma unroll
        for (int ni = 0; ni < 8; ni++)
            #pragma unroll
            for (int t2 = 0; t2 < 4; t2++) {
                const int q = t2 >> 1, t = t2 & 1;
                const int n = nw * 64 + ni * 8 + (l & 3) * 2 + t;
                float h = acc[mi][ni][t2] + s_b1[n];
                h = fmaxf(h, 0.0f);
                part[mi * 2 + q][0] = fmaf(h, s_W2[n * 3 + 0], part[mi * 2 + q][0]);
                part[mi * 2 + q][1] = fmaf(h, s_W2[n * 3 + 1], part[mi * 2 + q][1]);
                part[mi * 2 + q][2] = fmaf(h, s_W2[n * 3 + 2], part[mi * 2 + q][2]);
            }

    // reduce over the 4 lanes sharing each row (l&3 varies)
    #pragma unroll
    for (int r = 0; r < 8; r++)
        #pragma unroll
        for (int p = 0; p < 3; p++) {
            part[r][p] += __shfl_xor_sync(0xffffffffu, part[r][p], 1);
            part[r][p] += __shfl_xor_sync(0xffffffffu, part[r][p], 2);
        }

    if ((l & 3) == 0) {
        #pragma unroll
        for (int mi = 0; mi < 4; mi++)
            #pragma unroll
            for (int q = 0; q < 2; q++) {
                const int row = mw * 64 + mi * 16 + (l >> 2) + q * 8;
                atomicAdd(&s_red[row * 3 + 0], part[mi * 2 + q][0]);
                atomicAdd(&s_red[row * 3 + 1], part[mi * 2 + q][1]);
                atomicAdd(&s_red[row * 3 + 2], part[mi * 2 + q][2]);
            }
    }
    __syncthreads();

    if (tid < M_TILE) {
        float* po = out + (size_t)(mtile * M_TILE + tid) * (N_HEADS * D_OUT) + head * 3;
        po[0] = s_red[tid * 3 + 0] + s_b2[0];
        po[1] = s_red[tid * 3 + 1] + s_b2[1];
        po[2] = s_red[tid * 3 + 2] + s_b2[2];
    }
}

// ---------------- host launch ----------------
extern "C" void kernel_launch(void* const* d_in, const int* in_sizes, int n_in,
                              void* d_out, int out_size) {
    const float* X  = (const float*)d_in[0];
    const float* W1 = (const float*)d_in[1];
    const float* b1 = (const float*)d_in[2];
    const float* W2 = (const float*)d_in[3];
    const float* b2 = (const float*)d_in[4];
    float* out = (float*)d_out;
    (void)in_sizes; (void)n_in; (void)out_size;

    k_prepass<<<CONV_BLOCKS + TRANS_BLOCKS, 256>>>(X, W1);

    static bool attr_set = false;   // idempotent config, set before first (uncaptured) run
    if (!attr_set) {
        cudaFuncSetAttribute(k_gemm, cudaFuncAttributeMaxDynamicSharedMemorySize, SMEM_SIZE);
        attr_set = true;
    }
    dim3 grid(BATCH / M_TILE, N_HEADS);
    k_gemm<<<grid, 256, SMEM_SIZE>>>(b1, W2, b2, out);
}